// round 5
// baseline (speedup 1.0000x reference)
#include <cuda_runtime.h>
#include <cuda_bf16.h>
#include <cstdint>
#include <math.h>

#define B_   16
#define N_   1024
#define P_   8
#define H_   300
#define HP_  320
#define MT   64
#define NC   64
#define NCT  5      // 320/64 column tiles
#define KC   32
#define NKT  10     // 320/32 k-chunks

// ---------------- device-global scratch ----------------
__device__ __align__(16) __nv_bfloat16 g_Wh[P_ * HP_ * HP_];             // 1.6 MB
__device__ __align__(16) __nv_bfloat16 g_Wl[P_ * HP_ * HP_];             // 1.6 MB
__device__ __align__(16) __nv_bfloat16 g_Ah[(size_t)B_ * N_ * P_ * HP_]; // 84 MB
__device__ __align__(16) __nv_bfloat16 g_Al[(size_t)B_ * N_ * P_ * HP_]; // 84 MB
__device__ float g_partial[NCT * B_ * N_];

// ---------------- helpers ----------------
__device__ __forceinline__ float warp_sum(float v) {
#pragma unroll
    for (int o = 16; o; o >>= 1) v += __shfl_xor_sync(0xffffffffu, v, o);
    return v;
}
__device__ __forceinline__ float warp_max(float v) {
#pragma unroll
    for (int o = 16; o; o >>= 1) v = fmaxf(v, __shfl_xor_sync(0xffffffffu, v, o));
    return v;
}
__device__ __forceinline__ uint32_t smem_u32(const void* p) {
    uint32_t a;
    asm("{ .reg .u64 t; cvta.to.shared.u64 t, %1; cvt.u32.u64 %0, t; }" : "=r"(a) : "l"(p));
    return a;
}
__device__ __forceinline__ void cpa16(uint32_t dst, const void* src) {
    asm volatile("cp.async.cg.shared.global [%0], [%1], 16;" :: "r"(dst), "l"(src));
}
#define CPA_COMMIT() asm volatile("cp.async.commit_group;")
#define CPA_WAIT1()  asm volatile("cp.async.wait_group 1;")

__device__ __forceinline__ void ldm4(uint32_t* r, uint32_t a) {
    asm volatile("ldmatrix.sync.aligned.m8n8.x4.shared.b16 {%0,%1,%2,%3}, [%4];"
                 : "=r"(r[0]), "=r"(r[1]), "=r"(r[2]), "=r"(r[3]) : "r"(a));
}
__device__ __forceinline__ void mma_bf16(float* c, const uint32_t* a, const uint32_t* b) {
    asm("mma.sync.aligned.m16n8k16.row.col.f32.bf16.bf16.f32 "
        "{%0,%1,%2,%3},{%4,%5,%6,%7},{%8,%9},{%0,%1,%2,%3};"
        : "+f"(c[0]), "+f"(c[1]), "+f"(c[2]), "+f"(c[3])
        : "r"(a[0]), "r"(a[1]), "r"(a[2]), "r"(a[3]), "r"(b[0]), "r"(b[1]));
}

// ===========================================================================
// K1: g_W{h,l}[p][ko][h] = bf16split(W[p][h][ko])  (transposed, zero-padded)
// ===========================================================================
__global__ void prep_w(const float* __restrict__ W) {
    int idx = blockIdx.x * blockDim.x + threadIdx.x;
    const int total = P_ * HP_ * HP_;
    if (idx >= total) return;
    int h  = idx % HP_;
    int ko = (idx / HP_) % HP_;
    int p  = idx / (HP_ * HP_);
    float v = (h < H_ && ko < H_) ? W[((size_t)p * H_ + h) * H_ + ko] : 0.f;
    __nv_bfloat16 hi = __float2bfloat16_rn(v);
    __nv_bfloat16 lo = __float2bfloat16_rn(v - __bfloat162float(hi));
    g_Wh[idx] = hi;
    g_Wl[idx] = lo;
}

// ===========================================================================
// K2: g_A{h,l}[b][n][p][hp] = bf16split(instr[b][h] * na[b][n][p][h])
// ===========================================================================
__global__ void prep_a(const float* __restrict__ na, const float* __restrict__ instr) {
    int idx = blockIdx.x * blockDim.x + threadIdx.x;
    const int total = B_ * N_ * P_ * (HP_ / 4);
    if (idx >= total) return;
    int hq   = idx % (HP_ / 4);
    int rest = idx / (HP_ / 4);              // (b*N + n)*P + p
    int h    = hq * 4;
    int b    = rest >> 13;                   // / (N_*P_)
    float4 v = make_float4(0.f, 0.f, 0.f, 0.f);
    if (h < H_) {
        v = *(const float4*)(na + (size_t)rest * H_ + h);
        const float* ib = instr + b * H_ + h;
        v.x *= ib[0]; v.y *= ib[1]; v.z *= ib[2]; v.w *= ib[3];
    }
    __nv_bfloat16 h0 = __float2bfloat16_rn(v.x), h1 = __float2bfloat16_rn(v.y);
    __nv_bfloat16 h2 = __float2bfloat16_rn(v.z), h3 = __float2bfloat16_rn(v.w);
    __nv_bfloat16 l0 = __float2bfloat16_rn(v.x - __bfloat162float(h0));
    __nv_bfloat16 l1 = __float2bfloat16_rn(v.y - __bfloat162float(h1));
    __nv_bfloat16 l2 = __float2bfloat16_rn(v.z - __bfloat162float(h2));
    __nv_bfloat16 l3 = __float2bfloat16_rn(v.w - __bfloat162float(h3));
    uint2 hv = make_uint2(
        (uint32_t)__bfloat16_as_ushort(h0) | ((uint32_t)__bfloat16_as_ushort(h1) << 16),
        (uint32_t)__bfloat16_as_ushort(h2) | ((uint32_t)__bfloat16_as_ushort(h3) << 16));
    uint2 lv = make_uint2(
        (uint32_t)__bfloat16_as_ushort(l0) | ((uint32_t)__bfloat16_as_ushort(l1) << 16),
        (uint32_t)__bfloat16_as_ushort(l2) | ((uint32_t)__bfloat16_as_ushort(l3) << 16));
    *(uint2*)(g_Ah + (size_t)idx * 4) = hv;
    *(uint2*)(g_Al + (size_t)idx * 4) = lv;
}

// ===========================================================================
// K3: FUSED bf16x3 GEMM over all 8 p + sim fold + normalize + elu + wss dot
// grid (NCT, N/MT, B) = (5, 16, 16) = 1280; 256 thr = 8 warps (4m x 2n)
// warp tile 16x32; per-thread c[4][4], sacc[4][4], qacc[4][4]
// smem: 2 stages x [Ah 64x40h | Al | Bh 64x40h | Bl], row stride 80 B
// ===========================================================================
#define RSTR_B    80
#define TIL_BYTES (64 * RSTR_B)              // 5120 per tile
#define STG_BYTES (4 * TIL_BYTES)            // 20480 per stage
#define OAL  TIL_BYTES
#define OBH  (2 * TIL_BYTES)
#define OBL  (3 * TIL_BYTES)

__global__ __launch_bounds__(256, 2)
void fused_gemm(const float* __restrict__ sim, const float* __restrict__ wss) {
    extern __shared__ char smraw[];
    const uint32_t sbase = smem_u32(smraw);
    __shared__ float ssim[P_];
    __shared__ float swss[NC];
    __shared__ float red[2][MT];

    const int t = threadIdx.x, lane = t & 31, wid = t >> 5;
    const int g = lane >> 2, tq = lane & 3;
    const int b = blockIdx.z, m0 = blockIdx.y * MT, n0 = blockIdx.x * NC;
    const int wm = wid & 3, wn = wid >> 2;
    const int m_w = wm * 16, n_w = wn * 32;

    if (t < P_) ssim[t] = sim[b * P_ + t];
    if (t < NC) swss[t] = (n0 + t < H_) ? wss[n0 + t] : 0.f;

    // cp.async indexing: 256 thr -> 64 rows x 4 16B segments
    const int arow = t >> 2, aseg = t & 3;
    // ldmatrix lane offsets (same mapping validated in R4)
    const uint32_t aoff = (uint32_t)((lane & 15) * RSTR_B + ((lane >> 4) << 4));
    const uint32_t boff = (uint32_t)((((lane & 7) + ((lane >> 4) << 3)) * RSTR_B) +
                                     (((lane >> 3) & 1) << 4));

    auto issue = [&](int p, int kt, int s) {
        const uint32_t st = sbase + s * STG_BYTES;
        const int kh = kt * KC + aseg * 8;
        const uint32_t so = (uint32_t)(arow * RSTR_B + aseg * 16);
        size_t ga = ((size_t)((b * N_ + m0 + arow) * P_) + p) * HP_ + kh;
        cpa16(st + so, g_Ah + ga);
        cpa16(st + OAL + so, g_Al + ga);
        size_t gb = ((size_t)p * HP_ + n0 + arow) * HP_ + kh;
        cpa16(st + OBH + so, g_Wh + gb);
        cpa16(st + OBL + so, g_Wl + gb);
    };

    float c[4][4], sacc[4][4], qacc[4][4];
#pragma unroll
    for (int nf = 0; nf < 4; nf++)
#pragma unroll
        for (int e = 0; e < 4; e++) { sacc[nf][e] = 0.f; qacc[nf][e] = 0.f; }

    issue(0, 0, 0); CPA_COMMIT();
    issue(0, 1, 1); CPA_COMMIT();
    __syncthreads();   // ssim/swss visible

    int p = 0, kt = 0;
#pragma unroll 1
    for (int it = 0; it < P_ * NKT; ++it) {
        const int s = it & 1;
        CPA_WAIT1();
        __syncthreads();
        const uint32_t st = sbase + s * STG_BYTES;

        if (kt == 0) {
#pragma unroll
            for (int nf = 0; nf < 4; nf++)
#pragma unroll
                for (int e = 0; e < 4; e++) c[nf][e] = 0.f;
        }

#pragma unroll
        for (int kkI = 0; kkI < 2; kkI++) {
            const uint32_t kkb = kkI * 32;
            uint32_t ah[4], al[4], bh[2][4], bl[2][4];
            {
                uint32_t ba = st + (uint32_t)(m_w * RSTR_B) + kkb + aoff;
                ldm4(ah, ba);
                ldm4(al, ba + OAL);
            }
#pragma unroll
            for (int nfp = 0; nfp < 2; nfp++) {
                uint32_t bb = st + OBH + (uint32_t)((n_w + nfp * 16) * RSTR_B) + kkb + boff;
                ldm4(bh[nfp], bb);
                ldm4(bl[nfp], bb + TIL_BYTES);
            }
#pragma unroll
            for (int nf = 0; nf < 4; nf++) {
                const uint32_t* bhp = &bh[nf >> 1][(nf & 1) * 2];
                const uint32_t* blp = &bl[nf >> 1][(nf & 1) * 2];
                mma_bf16(c[nf], ah, bhp);   // hi*hi
                mma_bf16(c[nf], ah, blp);   // hi*lo
                mma_bf16(c[nf], al, bhp);   // lo*hi
            }
        }
        __syncthreads();

        // next chunk indices
        int pn = p, ktn = kt + 1;
        if (ktn == NKT) { ktn = 0; pn = p + 1; }
        if (it + 2 < P_ * NKT) {
            int p2 = p, kt2 = kt + 2;
            if (kt2 >= NKT) { kt2 -= NKT; p2 = p + 1; }
            if (kt2 >= NKT) { kt2 -= NKT; p2 = p + 2; }   // safe (NKT>=2)
            issue(p2, kt2, s);
        }
        CPA_COMMIT();

        if (kt == NKT - 1) {
            const float sp = ssim[p];
#pragma unroll
            for (int nf = 0; nf < 4; nf++)
#pragma unroll
                for (int e = 0; e < 4; e++) {
                    float sv = sp * c[nf][e];
                    sacc[nf][e] += sv;
                    qacc[nf][e] = fmaf(sv, sv, qacc[nf][e]);
                }
        }
        p = pn; kt = ktn;
    }

    // ---- epilogue in registers: normalize over P, elu, *wss, row-reduce ----
    float r0 = 0.f, r1 = 0.f;   // rows m_w+g, m_w+8+g (this warp's 32 cols)
#pragma unroll
    for (int nf = 0; nf < 4; nf++)
#pragma unroll
        for (int e = 0; e < 4; e++) {
            int col = n_w + nf * 8 + 2 * tq + (e & 1);
            float q = qacc[nf][e];
            float sv = sacc[nf][e];
            float nrm = fmaxf(sqrtf(q), 1e-12f);
            float sc = sv / nrm;
            float el = sc > 0.f ? sc : expm1f(sc);
            float v = el * swss[col];
            if (e < 2) r0 += v; else r1 += v;
        }
    r0 += __shfl_xor_sync(0xffffffffu, r0, 1);
    r0 += __shfl_xor_sync(0xffffffffu, r0, 2);
    r1 += __shfl_xor_sync(0xffffffffu, r1, 1);
    r1 += __shfl_xor_sync(0xffffffffu, r1, 2);
    if (tq == 0) {
        red[wn][m_w + g]     = r0;
        red[wn][m_w + 8 + g] = r1;
    }
    __syncthreads();
    if (t < MT)
        g_partial[((size_t)blockIdx.x * B_ + b) * N_ + m0 + t] = red[0][t] + red[1][t];
}

// ===========================================================================
// K4: combine partials + mask, softmax over N per batch
// ===========================================================================
__global__ __launch_bounds__(1024)
void softmax_kernel(const float* __restrict__ mask, float* __restrict__ out) {
    const int b = blockIdx.x, t = threadIdx.x;
    float v = mask[b * N_ + t];
#pragma unroll
    for (int i = 0; i < NCT; i++) v += g_partial[((size_t)i * B_ + b) * N_ + t];

    __shared__ float red[32];
    const int lane = t & 31, wid = t >> 5;

    float m = warp_max(v);
    if (lane == 0) red[wid] = m;
    __syncthreads();
    if (wid == 0) red[lane] = warp_max(red[lane]);
    __syncthreads();
    m = red[0];
    __syncthreads();

    float e = expf(v - m);
    float s = warp_sum(e);
    if (lane == 0) red[wid] = s;
    __syncthreads();
    if (wid == 0) red[lane] = warp_sum(red[lane]);
    __syncthreads();
    s = red[0];

    out[b * N_ + t] = e / s;
}

// ===========================================================================
extern "C" void kernel_launch(void* const* d_in, const int* in_sizes, int n_in,
                              void* d_out, int out_size) {
    const float* node_attr = (const float*)d_in[0];
    const float* instr     = (const float*)d_in[2];
    const float* sim       = (const float*)d_in[4];
    const float* mask      = (const float*)d_in[5];
    const float* W         = (const float*)d_in[6];
    const float* wss       = (const float*)d_in[7];
    float* out = (float*)d_out;

    cudaFuncSetAttribute(fused_gemm, cudaFuncAttributeMaxDynamicSharedMemorySize,
                         2 * STG_BYTES);

    const int totW = P_ * HP_ * HP_;
    prep_w<<<(totW + 255) / 256, 256>>>(W);

    const int totA = B_ * N_ * P_ * (HP_ / 4);
    prep_a<<<(totA + 255) / 256, 256>>>(node_attr, instr);

    dim3 gg(NCT, N_ / MT, B_);   // (5, 16, 16)
    fused_gemm<<<gg, 256, 2 * STG_BYTES>>>(sim, wss);

    softmax_kernel<<<B_, 1024>>>(mask, out);
}

// round 6
// speedup vs baseline: 1.3554x; 1.3554x over previous
#include <cuda_runtime.h>
#include <cstdint>
#include <math.h>

#define B_   16
#define N_   1024
#define P_   8
#define H_   300
#define HP_  320
#define MT   128
#define NC   64
#define NCT  5
#define KB   32      // int8 k-elems per chunk
#define NKT  10      // 320/32

#define QMAXF 16256.0f   // 127*128

// ---------------- device-global scratch ----------------
__device__ __align__(16) int8_t g_Aq[2ull * B_ * N_ * P_ * HP_];  // 84 MB (hi|lo limbs)
__device__ __align__(16) int8_t g_Wq[2ull * P_ * HP_ * HP_];      // 1.6 MB
__device__ float g_sA[B_ * N_ * P_];
__device__ float g_sB[P_ * HP_];
__device__ float g_Y[(size_t)B_ * P_ * N_ * HP_];                 // 168 MB
__device__ float g_logits[B_ * N_];

#define LIMBA ((size_t)B_ * N_ * P_ * HP_)
#define LIMBW ((size_t)P_ * HP_ * HP_)

// ---------------- helpers ----------------
__device__ __forceinline__ float warp_sum(float v) {
#pragma unroll
    for (int o = 16; o; o >>= 1) v += __shfl_xor_sync(0xffffffffu, v, o);
    return v;
}
__device__ __forceinline__ float warp_max(float v) {
#pragma unroll
    for (int o = 16; o; o >>= 1) v = fmaxf(v, __shfl_xor_sync(0xffffffffu, v, o));
    return v;
}
__device__ __forceinline__ uint32_t smem_u32(const void* p) {
    uint32_t a;
    asm("{ .reg .u64 t; cvta.to.shared.u64 t, %1; cvt.u32.u64 %0, t; }" : "=r"(a) : "l"(p));
    return a;
}
__device__ __forceinline__ void cpa16(uint32_t dst, const void* src) {
    asm volatile("cp.async.cg.shared.global [%0], [%1], 16;" :: "r"(dst), "l"(src));
}
#define CPA_COMMIT() asm volatile("cp.async.commit_group;")

__device__ __forceinline__ void ldm4(uint32_t* r, uint32_t a) {
    asm volatile("ldmatrix.sync.aligned.m8n8.x4.shared.b16 {%0,%1,%2,%3}, [%4];"
                 : "=r"(r[0]), "=r"(r[1]), "=r"(r[2]), "=r"(r[3]) : "r"(a));
}
__device__ __forceinline__ void mma_s8(int* c, const uint32_t* a, const uint32_t* b) {
    asm("mma.sync.aligned.m16n8k32.row.col.s32.s8.s8.s32 "
        "{%0,%1,%2,%3},{%4,%5,%6,%7},{%8,%9},{%0,%1,%2,%3};"
        : "+r"(c[0]), "+r"(c[1]), "+r"(c[2]), "+r"(c[3])
        : "r"(a[0]), "r"(a[1]), "r"(a[2]), "r"(a[3]), "r"(b[0]), "r"(b[1]));
}

// ===========================================================================
// K1: quantize W^T: per (p,ko) row over h, 14-bit 2-limb int8 + f32 scale
// ===========================================================================
__global__ void prep_w(const float* __restrict__ W) {
    int t = blockIdx.x * blockDim.x + threadIdx.x;
    if (t >= P_ * HP_) return;
    int p = t / HP_, ko = t % HP_;
    float amax = 0.f;
    if (ko < H_)
        for (int h = 0; h < H_; h++)
            amax = fmaxf(amax, fabsf(W[((size_t)p * H_ + h) * H_ + ko]));
    float inv = amax > 0.f ? QMAXF / amax : 0.f;
    g_sB[t] = amax > 0.f ? amax / QMAXF : 1.f;
    size_t base = (size_t)t * HP_;
    for (int h4 = 0; h4 < HP_ / 4; h4++) {
        uint32_t hw = 0, lw = 0;
#pragma unroll
        for (int e = 0; e < 4; e++) {
            int h = h4 * 4 + e;
            float w = (ko < H_ && h < H_) ? W[((size_t)p * H_ + h) * H_ + ko] : 0.f;
            int q = __float2int_rn(w * inv);
            int hi = (q + 64) >> 7;
            int lo = q - (hi << 7);
            hw |= ((uint32_t)(uint8_t)(int8_t)hi) << (8 * e);
            lw |= ((uint32_t)(uint8_t)(int8_t)lo) << (8 * e);
        }
        *(uint32_t*)(g_Wq + base + h4 * 4) = hw;
        *(uint32_t*)(g_Wq + LIMBW + base + h4 * 4) = lw;
    }
}

// ===========================================================================
// K2: quantize A: one warp per (b,n,p) row; fold instruction; 2-limb int8
// ===========================================================================
__global__ __launch_bounds__(256)
void prep_a(const float* __restrict__ na, const float* __restrict__ instr) {
    int gw = (blockIdx.x * blockDim.x + threadIdx.x) >> 5;
    int lane = threadIdx.x & 31;
    if (gw >= B_ * N_ * P_) return;
    int b = gw >> 13;                       // / (N_*P_)
    const float* src = na + (size_t)gw * H_;
    const float* ib  = instr + b * H_;
    float v[10];
    float amax = 0.f;
#pragma unroll
    for (int j = 0; j < 10; j++) {
        int idx = lane + 32 * j;
        float x = (idx < H_) ? src[idx] * ib[idx] : 0.f;
        v[j] = x;
        amax = fmaxf(amax, fabsf(x));
    }
    amax = warp_max(amax);
    float inv = amax > 0.f ? QMAXF / amax : 0.f;
    if (lane == 0) g_sA[gw] = amax > 0.f ? amax / QMAXF : 1.f;
    size_t base = (size_t)gw * HP_;
#pragma unroll
    for (int j = 0; j < 10; j++) {
        int idx = lane + 32 * j;
        int q = __float2int_rn(v[j] * inv);
        int hi = (q + 64) >> 7;
        int lo = q - (hi << 7);
        g_Aq[base + idx] = (int8_t)hi;
        g_Aq[LIMBA + base + idx] = (int8_t)lo;
    }
}

// ===========================================================================
// K3: batched int8 2-limb GEMM, 3-stage cp.async, 1 sync/chunk
// grid (NCT, N/MT, B*P) = (5, 8, 128); 256 thr = 8 warps (4m x 2n), warp 32x32
// smem/stage: Ahi 128x48B | Alo | Bhi 64x48B | Blo = 18432 B; x3 = 55296 B
// ===========================================================================
#define RSTR  48
#define A_T   (128 * RSTR)          // 6144
#define Bt_T  (64 * RSTR)           // 3072
#define STG   (2 * A_T + 2 * Bt_T)  // 18432
#define OAL   A_T
#define OBH   (2 * A_T)
#define NSTG  3

__global__ __launch_bounds__(256, 2)
void gemm() {
    extern __shared__ char smraw[];
    const uint32_t sbase = smem_u32(smraw);

    const int t = threadIdx.x, lane = t & 31, wid = t >> 5;
    const int g = lane >> 2, tq = lane & 3;
    const int bp = blockIdx.z, b = bp >> 3, p = bp & 7;
    const int m0 = blockIdx.y * MT, n0 = blockIdx.x * NC;
    const int wm = wid & 3, wn = wid >> 2;
    const int m_w = wm * 32, n_w = wn * 32;

    // cp.async indexing: A: 128 rows x 2 segs per limb; B: 64 rows x 2 segs x 2 limbs
    const int arow = t >> 1, aseg = t & 1;
    const int brow = t >> 2, blimb = (t >> 1) & 1, bseg = t & 1;
    // ldmatrix lane offsets (geometry proven in R4, stride swapped to 48B)
    const uint32_t aoff = (uint32_t)((lane & 15) * RSTR + ((lane >> 4) << 4));
    const uint32_t boff = (uint32_t)((((lane & 7) + ((lane >> 4) << 3)) * RSTR) +
                                     (((lane >> 3) & 1) << 4));

    const size_t agbase = ((size_t)((b * N_ + m0 + arow) * P_) + p) * HP_;
    const size_t bgbase = ((size_t)p * HP_ + n0 + brow) * HP_;

    auto issue = [&](int kt, int s) {
        const uint32_t st = sbase + s * STG;
        {
            const int kh = kt * KB + aseg * 16;
            const uint32_t so = (uint32_t)(arow * RSTR + aseg * 16);
            cpa16(st + so, g_Aq + agbase + kh);
            cpa16(st + OAL + so, g_Aq + LIMBA + agbase + kh);
        }
        {
            const int kh = kt * KB + bseg * 16;
            const uint32_t so = (uint32_t)(brow * RSTR + bseg * 16);
            cpa16(st + OBH + blimb * Bt_T + so, g_Wq + blimb * LIMBW + bgbase + kh);
        }
    };

    int chh[2][4][4], cmd[2][4][4];
#pragma unroll
    for (int mf = 0; mf < 2; mf++)
#pragma unroll
        for (int nf = 0; nf < 4; nf++)
#pragma unroll
            for (int e = 0; e < 4; e++) { chh[mf][nf][e] = 0; cmd[mf][nf][e] = 0; }

    issue(0, 0); CPA_COMMIT();
    issue(1, 1); CPA_COMMIT();

#pragma unroll 1
    for (int kt = 0; kt < NKT; kt++) {
        const int s = kt % NSTG;
        asm volatile("cp.async.wait_group 1;");
        __syncthreads();
        if (kt + 2 < NKT) issue(kt + 2, (kt + 2) % NSTG);
        CPA_COMMIT();

        const uint32_t st = sbase + s * STG;
        uint32_t ah[2][4], al[2][4], bh[2][4], blr[2][4];
#pragma unroll
        for (int mf = 0; mf < 2; mf++) {
            uint32_t ba = st + (uint32_t)((m_w + mf * 16) * RSTR) + aoff;
            ldm4(ah[mf], ba);
            ldm4(al[mf], ba + OAL);
        }
#pragma unroll
        for (int nfp = 0; nfp < 2; nfp++) {
            uint32_t bb = st + OBH + (uint32_t)((n_w + nfp * 16) * RSTR) + boff;
            ldm4(bh[nfp], bb);
            ldm4(blr[nfp], bb + Bt_T);
        }
#pragma unroll
        for (int mf = 0; mf < 2; mf++)
#pragma unroll
            for (int nf = 0; nf < 4; nf++) {
                const uint32_t* ph = &bh[nf >> 1][(nf & 1) * 2];
                const uint32_t* pl = &blr[nf >> 1][(nf & 1) * 2];
                mma_s8(chh[mf][nf], ah[mf], ph);   // hi*hi   (<<14)
                mma_s8(cmd[mf][nf], ah[mf], pl);   // hi*lo   (<<7)
                mma_s8(cmd[mf][nf], al[mf], ph);   // lo*hi   (<<7)
            }
    }

    // ---- apply scales, store Y ----
    float sa[2][2];
#pragma unroll
    for (int mf = 0; mf < 2; mf++)
#pragma unroll
        for (int hh = 0; hh < 2; hh++) {
            int row = m0 + m_w + mf * 16 + g + hh * 8;
            sa[mf][hh] = g_sA[(b * N_ + row) * P_ + p];
        }

    float* yb = g_Y + (size_t)(b * P_ + p) * N_ * HP_;
#pragma unroll
    for (int mf = 0; mf < 2; mf++)
#pragma unroll
        for (int nf = 0; nf < 4; nf++) {
            int gr = m0 + m_w + mf * 16 + g;
            int gc = n0 + n_w + nf * 8 + 2 * tq;
            float2 sb2 = *(const float2*)(g_sB + p * HP_ + gc);
            float v0 = (float)chh[mf][nf][0] * 16384.f + (float)cmd[mf][nf][0] * 128.f;
            float v1 = (float)chh[mf][nf][1] * 16384.f + (float)cmd[mf][nf][1] * 128.f;
            float v2 = (float)chh[mf][nf][2] * 16384.f + (float)cmd[mf][nf][2] * 128.f;
            float v3 = (float)chh[mf][nf][3] * 16384.f + (float)cmd[mf][nf][3] * 128.f;
            *(float2*)(yb + (size_t)gr * HP_ + gc) =
                make_float2(sa[mf][0] * sb2.x * v0, sa[mf][0] * sb2.y * v1);
            *(float2*)(yb + (size_t)(gr + 8) * HP_ + gc) =
                make_float2(sa[mf][1] * sb2.x * v2, sa[mf][1] * sb2.y * v3);
        }
}

// ===========================================================================
// K4: per-(b,n): sv = sim_p*y; normalize over P; elu; dot wss; + mask
// ===========================================================================
__global__ __launch_bounds__(256)
void epilogue(const float* __restrict__ sim,
              const float* __restrict__ wss,
              const float* __restrict__ mask) {
    const int bn = blockIdx.x;
    const int b  = bn >> 10;
    const int n  = bn & 1023;
    const float* base = g_Y + ((size_t)b * P_ * N_ + n) * HP_;

    float sp[P_];
#pragma unroll
    for (int p = 0; p < P_; p++) sp[p] = sim[b * P_ + p];

    float acc = 0.f;
    for (int k = threadIdx.x; k < H_; k += 256) {
        float s = 0.f, q = 0.f;
#pragma unroll
        for (int p = 0; p < P_; p++) {
            float v = sp[p] * base[(size_t)p * (N_ * HP_) + k];
            s += v;
            q = fmaf(v, v, q);
        }
        float nrm = fmaxf(sqrtf(q), 1e-12f);
        float sc  = s / nrm;
        float e   = sc > 0.f ? sc : expm1f(sc);
        acc += e * wss[k];
    }
    acc = warp_sum(acc);
    __shared__ float ws[8];
    int lane = threadIdx.x & 31, wid = threadIdx.x >> 5;
    if (lane == 0) ws[wid] = acc;
    __syncthreads();
    if (threadIdx.x == 0) {
        float s = 0.f;
#pragma unroll
        for (int i = 0; i < 8; i++) s += ws[i];
        g_logits[bn] = s + mask[bn];
    }
}

// ===========================================================================
// K5: softmax over N per batch
// ===========================================================================
__global__ __launch_bounds__(1024)
void softmax_kernel(float* __restrict__ out) {
    const int b = blockIdx.x, t = threadIdx.x;
    float v = g_logits[b * N_ + t];
    __shared__ float red[32];
    const int lane = t & 31, wid = t >> 5;

    float m = warp_max(v);
    if (lane == 0) red[wid] = m;
    __syncthreads();
    if (wid == 0) red[lane] = warp_max(red[lane]);
    __syncthreads();
    m = red[0];
    __syncthreads();

    float e = expf(v - m);
    float s = warp_sum(e);
    if (lane == 0) red[wid] = s;
    __syncthreads();
    if (wid == 0) red[lane] = warp_sum(red[lane]);
    __syncthreads();
    s = red[0];

    out[b * N_ + t] = e / s;
}

// ===========================================================================
extern "C" void kernel_launch(void* const* d_in, const int* in_sizes, int n_in,
                              void* d_out, int out_size) {
    const float* node_attr = (const float*)d_in[0];
    const float* instr     = (const float*)d_in[2];
    const float* sim       = (const float*)d_in[4];
    const float* mask      = (const float*)d_in[5];
    const float* W         = (const float*)d_in[6];
    const float* wss       = (const float*)d_in[7];
    float* out = (float*)d_out;

    cudaFuncSetAttribute(gemm, cudaFuncAttributeMaxDynamicSharedMemorySize, NSTG * STG);

    prep_w<<<(P_ * HP_ + 255) / 256, 256>>>(W);

    const int nwarps = B_ * N_ * P_;          // one warp per row
    prep_a<<<nwarps / 8, 256>>>(node_attr, instr);

    dim3 gg(NCT, N_ / MT, B_ * P_);           // (5, 8, 128)
    gemm<<<gg, 256, NSTG * STG>>>();

    epilogue<<<B_ * N_, 256>>>(sim, wss, mask);

    softmax_kernel<<<B_, 1024>>>(out);
}